// round 10
// baseline (speedup 1.0000x reference)
#include <cuda_runtime.h>
#include <cuda_fp16.h>
#include <cstdint>
#include <math.h>

#define NN 50000
#define NE 800000
#define INDIM 128
#define HID 64
#define NSCH 49   // ceil(NN/1024)

// ======================= device scratch =======================
__device__ int    g_deg[NN];          // static-zeroed; re-zeroed by k_scan23
__device__ int    g_row_start[NN + 1];
__device__ int    g_cursor[NN];
__device__ int    g_csr[NE];
__device__ float  g_invdeg[NN];
__device__ int    g_psum[64];
__device__ float  g_y[NN * HID];
__device__ float  g_h1[NN * HID];
__device__ float  g_y2[NN * HID];
__device__ __half g_RS[NN * 128];     // [R|S] fp16 per node
__device__ float  g_zeros[128];

// ======================= CSR build =======================
__global__ void k_count(const int* __restrict__ dst) {
    int e = blockIdx.x * blockDim.x + threadIdx.x;
    if (e < NE) atomicAdd(&g_deg[dst[e]], 1);
}

__global__ void __launch_bounds__(1024) k_scan1() {
    __shared__ int wsum[32];
    int tid = threadIdx.x;
    int i = blockIdx.x * 1024 + tid;
    int v = (i < NN) ? g_deg[i] : 0;
    int xv = v;
    #pragma unroll
    for (int o = 1; o < 32; o <<= 1) {
        int y = __shfl_up_sync(0xffffffffu, xv, o);
        if ((tid & 31) >= o) xv += y;
    }
    if ((tid & 31) == 31) wsum[tid >> 5] = xv;
    __syncthreads();
    if (tid < 32) {
        int s = wsum[tid];
        #pragma unroll
        for (int o = 1; o < 32; o <<= 1) {
            int y = __shfl_up_sync(0xffffffffu, s, o);
            if (tid >= o) s += y;
        }
        wsum[tid] = s;
    }
    __syncthreads();
    int add = (tid >= 32) ? wsum[(tid >> 5) - 1] : 0;
    if (i < NN) g_row_start[i] = xv + add - v;
    if (tid == 0) g_psum[blockIdx.x] = wsum[31];
}

// Fused: scan the 49 chunk sums (redundantly per block) + apply + init + deg reset.
__global__ void __launch_bounds__(1024) k_scan23() {
    __shared__ int sexc[64];
    __shared__ int wtot;
    int tid = threadIdx.x;
    int v = 0, x = 0;
    if (tid < 64) {
        v = (tid < NSCH) ? g_psum[tid] : 0;
        x = v;
        #pragma unroll
        for (int o = 1; o < 32; o <<= 1) {
            int y = __shfl_up_sync(0xffffffffu, x, o);
            if ((tid & 31) >= o) x += y;
        }
        if (tid == 31) wtot = x;
    }
    __syncthreads();
    if (tid < 64) {
        int incl = x + ((tid >= 32) ? wtot : 0);
        sexc[tid] = incl - v;
        if (tid == NSCH - 1) g_row_start[NN] = incl;
    }
    __syncthreads();
    int off = sexc[blockIdx.x];
    int i = blockIdx.x * 1024 + tid;
    if (i < NN) {
        int rs = g_row_start[i] + off;
        g_row_start[i] = rs;
        g_cursor[i]    = rs;
        g_invdeg[i]    = 1.0f / fmaxf((float)g_deg[i], 1.0f);
        g_deg[i]       = 0;   // reset for next launch (deterministic)
    }
}

__global__ void k_bucket(const int* __restrict__ src, const int* __restrict__ dst) {
    int e = blockIdx.x * blockDim.x + threadIdx.x;
    if (e < NE) {
        int d = dst[e];
        int p = atomicAdd(&g_cursor[d], 1);
        g_csr[p] = src[e];
    }
}

// ======= mean aggregation (fused bias + relu): out = relu(y + agg(y)/deg + b)
__global__ void __launch_bounds__(256) k_aggr(const float* __restrict__ y,
                                              const float* __restrict__ bias,
                                              float* __restrict__ out) {
    int node = blockIdx.x * 16 + (threadIdx.x >> 4);
    int c4 = (threadIdx.x & 15) * 4;
    int beg = g_row_start[node], end = g_row_start[node + 1];
    float4 acc = make_float4(0.f, 0.f, 0.f, 0.f);
    int e = beg;
    for (; e + 7 < end; e += 8) {
        int sI[8];
        #pragma unroll
        for (int u = 0; u < 8; u++) sI[u] = __ldg(&g_csr[e + u]);
        float4 v[8];
        #pragma unroll
        for (int u = 0; u < 8; u++)
            v[u] = *reinterpret_cast<const float4*>(y + (size_t)sI[u] * 64 + c4);
        #pragma unroll
        for (int u = 0; u < 8; u++) {
            acc.x += v[u].x; acc.y += v[u].y;
            acc.z += v[u].z; acc.w += v[u].w;
        }
    }
    for (; e < end; e++) {
        int s = __ldg(&g_csr[e]);
        float4 v = *reinterpret_cast<const float4*>(y + (size_t)s * 64 + c4);
        acc.x += v.x; acc.y += v.y; acc.z += v.z; acc.w += v.w;
    }
    float inv = g_invdeg[node];
    float4 self = *reinterpret_cast<const float4*>(y + (size_t)node * 64 + c4);
    float4 b = *reinterpret_cast<const float4*>(bias + c4);
    float4 r;
    r.x = fmaxf(self.x + acc.x * inv + b.x, 0.0f);
    r.y = fmaxf(self.y + acc.y * inv + b.y, 0.0f);
    r.z = fmaxf(self.z + acc.z * inv + b.z, 0.0f);
    r.w = fmaxf(self.w + acc.w * inv + b.w, 0.0f);
    *reinterpret_cast<float4*>(out + (size_t)node * 64 + c4) = r;
}

// ============ dense GEMM with packed f32x2: out = Z @ W + bias ============
#define FMA2(c, a, b) asm("fma.rn.f32x2 %0, %1, %2, %3;" \
                          : "=l"(c) : "l"(a), "l"(b), "l"(c))
__device__ __forceinline__ unsigned long long pk(float lo, float hi) {
    unsigned long long r = (unsigned long long)__float_as_uint(lo);
    return r | ((unsigned long long)__float_as_uint(hi) << 32);
}

#define GRT 40
#define GNT 320
template <int K>
__global__ void __launch_bounds__(GNT) k_gemm(const float* __restrict__ Z,
                                              const float* __restrict__ W,
                                              const float* __restrict__ bias,
                                              float* __restrict__ out) {
    constexpr int KP = K + 4;
    constexpr int PSTR = 2 * K + 8;
    extern __shared__ float smg[];
    float* Ws  = smg;
    float* Zs2 = smg + 64 * KP;
    int tid = threadIdx.x;
    int j = tid % 64, rg = tid / 64;
    for (int idx = tid; idx < K * 64; idx += GNT) {
        int k = idx >> 6, c = idx & 63;
        Ws[c * KP + k] = W[idx];
    }
    int row0 = blockIdx.x * GRT;
    for (int idx = tid; idx < GRT * (K / 4); idx += GNT) {
        int r = idx / (K / 4), kq = idx % (K / 4);
        float4 v = reinterpret_cast<const float4*>(Z + (size_t)(row0 + r) * K)[kq];
        float* zb = Zs2 + (r >> 1) * PSTR + (r & 1) + 8 * kq;
        zb[0] = v.x; zb[2] = v.y; zb[4] = v.z; zb[6] = v.w;
    }
    __syncthreads();
    float bj = bias[j];
    unsigned long long acc2[4];
    #pragma unroll
    for (int rp = 0; rp < 4; rp++) acc2[rp] = pk(bj, bj);
    const float4* w4 = reinterpret_cast<const float4*>(&Ws[j * KP]);
    #pragma unroll 8
    for (int k4 = 0; k4 < K / 4; k4++) {
        float4 w = w4[k4];
        unsigned long long w0 = pk(w.x, w.x), w1 = pk(w.y, w.y);
        unsigned long long w2 = pk(w.z, w.z), w3 = pk(w.w, w.w);
        #pragma unroll
        for (int rp = 0; rp < 4; rp++) {
            const ulonglong2* zp = reinterpret_cast<const ulonglong2*>(
                &Zs2[(rg * 4 + rp) * PSTR + 8 * k4]);
            ulonglong2 A = zp[0], B = zp[1];
            FMA2(acc2[rp], A.x, w0);
            FMA2(acc2[rp], A.y, w1);
            FMA2(acc2[rp], B.x, w2);
            FMA2(acc2[rp], B.y, w3);
        }
    }
    #pragma unroll
    for (int rp = 0; rp < 4; rp++) {
        float lo = __uint_as_float((unsigned)acc2[rp]);
        float hi = __uint_as_float((unsigned)(acc2[rp] >> 32));
        out[(size_t)(row0 + rg * 8 + 2 * rp) * 64 + j]     = lo;
        out[(size_t)(row0 + rg * 8 + 2 * rp + 1) * 64 + j] = hi;
    }
}

// ============ RS precompute: RS[n] = [H@We1_top | H@We1_bot] -> fp16 ============
// 512 threads, 40 rows/block, f32x2 mainloop. No bias (be1 added in edge epilogue).
__global__ void __launch_bounds__(512) k_rs(const float* __restrict__ H,
                                            const float* __restrict__ We1,
                                            __half* __restrict__ RS) {
    __shared__ float Ws[128 * 68];      // [j'][k], KP=68
    __shared__ float Zs2[20 * 136];     // row pairs
    int tid = threadIdx.x;
    int j = tid & 127, rg = tid >> 7;   // rg 0..3, 5 row-pairs each
    for (int idx = tid; idx < 64 * 128; idx += 512) {
        int k = idx >> 7, jj = idx & 127;
        float val = (jj < 64) ? We1[k * 64 + jj]
                              : We1[(64 + k) * 64 + (jj - 64)];
        Ws[jj * 68 + k] = val;
    }
    int row0 = blockIdx.x * 40;
    for (int idx = tid; idx < 40 * 16; idx += 512) {
        int r = idx >> 4, kq = idx & 15;
        float4 v = reinterpret_cast<const float4*>(H + (size_t)(row0 + r) * 64)[kq];
        float* zb = Zs2 + (r >> 1) * 136 + (r & 1) + 8 * kq;
        zb[0] = v.x; zb[2] = v.y; zb[4] = v.z; zb[6] = v.w;
    }
    __syncthreads();
    unsigned long long acc2[5];
    #pragma unroll
    for (int rp = 0; rp < 5; rp++) acc2[rp] = 0ull;
    const float4* w4 = reinterpret_cast<const float4*>(&Ws[j * 68]);
    #pragma unroll 4
    for (int k4 = 0; k4 < 16; k4++) {
        float4 w = w4[k4];
        unsigned long long w0 = pk(w.x, w.x), w1 = pk(w.y, w.y);
        unsigned long long w2 = pk(w.z, w.z), w3 = pk(w.w, w.w);
        #pragma unroll
        for (int rp = 0; rp < 5; rp++) {
            const ulonglong2* zp = reinterpret_cast<const ulonglong2*>(
                &Zs2[(rg * 5 + rp) * 136 + 8 * k4]);
            ulonglong2 A = zp[0], B = zp[1];
            FMA2(acc2[rp], A.x, w0);
            FMA2(acc2[rp], A.y, w1);
            FMA2(acc2[rp], B.x, w2);
            FMA2(acc2[rp], B.y, w3);
        }
    }
    #pragma unroll
    for (int rp = 0; rp < 5; rp++) {
        int r0 = row0 + 2 * (rg * 5 + rp);
        RS[(size_t)r0 * 128 + j] =
            __float2half(__uint_as_float((unsigned)acc2[rp]));
        RS[(size_t)(r0 + 1) * 128 + j] =
            __float2half(__uint_as_float((unsigned)(acc2[rp] >> 32)));
    }
}

// ======================= fused edge MLP: K=128 pipelined mma.sync =======================
// A'[128e x 128k] = [p|q] fp16. B = fp16(We1 bilinear rows) in registers.
// dacc init = R[src]+S[dst] (fp16 rows staged with raw H via cp.async).
#define ET 128
#define ETILES (NE / ET)         // 6250
#define ROWB2 272                // A row: 128 halfs + pad
#define RAWB2 816                // hs@0(256) hd@272(256) R@544(128) S@672(128) pad
#define OFF_AH 1024
#define OFF_RAW (OFF_AH + 128 * ROWB2)       // 35840
#define SMEM_EDGE (OFF_RAW + 128 * RAWB2)    // 140288

__device__ __forceinline__ uint32_t smem_u32(const void* p) {
    uint32_t a;
    asm("{ .reg .u64 t; cvta.to.shared.u64 t, %1; cvt.u32.u64 %0, t; }"
        : "=r"(a) : "l"(p));
    return a;
}

#define CP16(d, s) asm volatile("cp.async.cg.shared.global [%0], [%1], 16;" \
                                :: "r"(d), "l"(s))
#define CP_COMMIT() asm volatile("cp.async.commit_group;" ::: "memory")
#define CP_WAIT0()  asm volatile("cp.async.wait_group 0;" ::: "memory")

#define LDSM4(r, addr)                                                         \
    asm volatile("ldmatrix.sync.aligned.m8n8.x4.shared.b16 {%0,%1,%2,%3}, [%4];" \
                 : "=r"((r)[0]), "=r"((r)[1]), "=r"((r)[2]), "=r"((r)[3])      \
                 : "r"(addr))

#define MMA16816(d, a, b)                                                      \
    asm volatile("mma.sync.aligned.m16n8k16.row.col.f32.f16.f16.f32 "          \
                 "{%0,%1,%2,%3},{%4,%5,%6,%7},{%8,%9},{%0,%1,%2,%3};"          \
                 : "+f"((d)[0]), "+f"((d)[1]), "+f"((d)[2]), "+f"((d)[3])      \
                 : "r"((a)[0]), "r"((a)[1]), "r"((a)[2]), "r"((a)[3]),         \
                   "r"((b)[0]), "r"((b)[1]))

__device__ __forceinline__ void write8h(char* ah, int koff2, const float* v) {
    uint32_t hi[4];
    #pragma unroll
    for (int i = 0; i < 4; i++) {
        __half2 h = __floats2half2_rn(v[2 * i], v[2 * i + 1]);
        hi[i] = *reinterpret_cast<uint32_t*>(&h);
    }
    *reinterpret_cast<uint4*>(ah + koff2) = make_uint4(hi[0], hi[1], hi[2], hi[3]);
}

__global__ void __launch_bounds__(256, 1) k_edge(
    const float* __restrict__ H, const __half* __restrict__ RS,
    const int* __restrict__ src, const int* __restrict__ dst,
    const float* __restrict__ We1, const float* __restrict__ be1,
    const float* __restrict__ We2, const float* __restrict__ be2,
    float* __restrict__ logits, float* __restrict__ probs) {
    extern __shared__ char sm[];
    float* sred = reinterpret_cast<float*>(sm);
    char* AhB  = sm + OFF_AH;
    char* rawB = sm + OFF_RAW;

    int tid = threadIdx.x, lane = tid & 31, wid = tid >> 5;
    int mw = wid & 3, nw = wid >> 2;

    // ---- B fragments (bilinear rows 128..255 of We1), K=128 -> 8 k-steps ----
    uint32_t bF[8][4][2];
    #pragma unroll
    for (int s = 0; s < 8; s++)
        #pragma unroll
        for (int j = 0; j < 4; j++)
            #pragma unroll
            for (int r = 0; r < 2; r++) {
                int k = s * 16 + 2 * (lane & 3) + r * 8;
                int n = nw * 32 + j * 8 + (lane >> 2);
                __half2 h = __floats2half2_rn(__ldg(&We1[(128 + k) * 64 + n]),
                                              __ldg(&We1[(129 + k) * 64 + n]));
                bF[s][j][r] = *reinterpret_cast<uint32_t*>(&h);
            }
    float bb[4][2], ww[4][2];
    #pragma unroll
    for (int j = 0; j < 4; j++)
        #pragma unroll
        for (int c = 0; c < 2; c++) {
            int nc = nw * 32 + j * 8 + 2 * (lane & 3) + c;
            bb[j][c] = __ldg(&be1[nc]);
            ww[j][c] = __ldg(&We2[nc]);
        }
    float be2v = be2[0];

    int el = tid >> 1, q = tid & 1;    // staging: edge el, half q
    const int* idxp = q ? dst : src;   // q=0: hs+R(src); q=1: hd+S(dst)
    uint32_t rawBase = smem_u32(rawB);
    uint32_t rawDstH  = rawBase + el * RAWB2 + q * 272;
    uint32_t rawDstRS = rawBase + el * RAWB2 + 544 + q * 128;
    uint32_t AhAddr = smem_u32(AhB);
    uint32_t mrow = (uint32_t)(mw * 32 + (lane & 15)) * ROWB2 + (lane >> 4) * 16;
    int G = gridDim.x;

    // ---- prologue prefetch ----
    int tile0 = blockIdx.x;
    {
        int n0 = __ldg(&idxp[tile0 * ET + el]);
        const char* s0 = (const char*)(H + (size_t)n0 * 64);
        #pragma unroll
        for (int k = 0; k < 16; k++) CP16(rawDstH + k * 16, s0 + k * 16);
        const char* r0 = (const char*)(RS + (size_t)n0 * 128) + q * 128;
        #pragma unroll
        for (int k = 0; k < 8; k++) CP16(rawDstRS + k * 16, r0 + k * 16);
        CP_COMMIT();
    }
    int tnext = tile0 + G;
    int nnext = (tnext < ETILES) ? __ldg(&idxp[tnext * ET + el]) : 0;

    for (int tile = tile0; tile < ETILES; tile += G) {
        int e0 = tile * ET;
        CP_WAIT0();
        __syncthreads();   // raw[tile] visible

        // ---- convert: fp32 hs,hd (smem) -> fp16 [p|q] ----
        {
            const float4* rhs = reinterpret_cast<const float4*>(
                rawB + el * RAWB2 + q * 128);
            const float4* rhd = reinterpret_cast<const float4*>(
                rawB + el * RAWB2 + 272 + q * 128);
            char* rAh = AhB + el * ROWB2;
            #pragma unroll
            for (int c = 0; c < 2; c++) {
                float4 a0 = rhs[2 * c], a1 = rhs[2 * c + 1];
                float4 b0 = rhd[2 * c], b1 = rhd[2 * c + 1];
                float p8[8], q8[8];
                float hs8[8] = {a0.x, a0.y, a0.z, a0.w, a1.x, a1.y, a1.z, a1.w};
                float hd8[8] = {b0.x, b0.y, b0.z, b0.w, b1.x, b1.y, b1.z, b1.w};
                #pragma unroll
                for (int i = 0; i < 8; i++) {
                    p8[i] = hs8[i] * hd8[i];
                    q8[i] = fabsf(hs8[i] - hd8[i]);
                }
                write8h(rAh, (q * 32 + 8 * c) * 2, p8);
                write8h(rAh, (64 + q * 32 + 8 * c) * 2, q8);
            }
            // remaining 16 cols of this thread's 32-col half
            #pragma unroll
            for (int c = 2; c < 4; c++) {
                float4 a0 = rhs[2 * c], a1 = rhs[2 * c + 1];
                float4 b0 = rhd[2 * c], b1 = rhd[2 * c + 1];
                float p8[8], q8[8];
                float hs8[8] = {a0.x, a0.y, a0.z, a0.w, a1.x, a1.y, a1.z, a1.w};
                float hd8[8] = {b0.x, b0.y, b0.z, b0.w, b1.x, b1.y, b1.z, b1.w};
                #pragma unroll
                for (int i = 0; i < 8; i++) {
                    p8[i] = hs8[i] * hd8[i];
                    q8[i] = fabsf(hs8[i] - hd8[i]);
                }
                write8h(rAh, (q * 32 + 8 * c) * 2, p8);
                write8h(rAh, (64 + q * 32 + 8 * c) * 2, q8);
            }
        }

        // ---- dacc init = R[src] + S[dst] (reads raw RS region) ----
        float dacc[2][4][4];
        #pragma unroll
        for (int t = 0; t < 2; t++) {
            int rowA = mw * 32 + t * 16 + (lane >> 2);
            int rowB = rowA + 8;
            #pragma unroll
            for (int j = 0; j < 4; j++) {
                int cb = nw * 32 + j * 8 + 2 * (lane & 3);
                const char* pa = rawB + rowA * RAWB2 + 544 + cb * 2;
                const char* pb = rawB + rowB * RAWB2 + 544 + cb * 2;
                __half2 ra_s = *reinterpret_cast<const __half2*>(pa);
                __half2 ra_d = *reinterpret_cast<const __half2*>(pa + 128);
                __half2 rb_s = *reinterpret_cast<const __half2*>(pb);
                __half2 rb_d = *reinterpret_cast<const __half2*>(pb + 128);
                float2 fa_s = __half22float2(ra_s), fa_d = __half22float2(ra_d);
                float2 fb_s = __half22float2(rb_s), fb_d = __half22float2(rb_d);
                dacc[t][j][0] = fa_s.x + fa_d.x;
                dacc[t][j][1] = fa_s.y + fa_d.y;
                dacc[t][j][2] = fb_s.x + fb_d.x;
                dacc[t][j][3] = fb_s.y + fb_d.y;
            }
        }
        __syncthreads();   // A ready; raw fully consumed

        // ---- prefetch next tile (overlaps MMA + epilogue) ----
        int tn = tile + G;
        if (tn < ETILES) {
            const char* sN = (const char*)(H + (size_t)nnext * 64);
            #pragma unroll
            for (int k = 0; k < 16; k++) CP16(rawDstH + k * 16, sN + k * 16);
            const char* rN = (const char*)(RS + (size_t)nnext * 128) + q * 128;
            #pragma unroll
            for (int k = 0; k < 8; k++) CP16(rawDstRS + k * 16, rN + k * 16);
            CP_COMMIT();
            int tnn = tn + G;
            if (tnn < ETILES) nnext = __ldg(&idxp[tnn * ET + el]);
        }

        // ---- MMA: K=128, single fp16 pass ----
        uint32_t base = AhAddr + mrow;
        #pragma unroll
        for (int s = 0; s < 8; s++) {
            uint32_t a0[4], a1[4];
            LDSM4(a0, base + s * 32);
            LDSM4(a1, base + 16 * ROWB2 + s * 32);
            #pragma unroll
            for (int j = 0; j < 4; j++) {
                MMA16816(dacc[0][j], a0, bF[s][j]);
                MMA16816(dacc[1][j], a1, bF[s][j]);
            }
        }

        // ---- epilogue: relu(D+be1).We2, quad reduce, smem combine ----
        #pragma unroll
        for (int t = 0; t < 2; t++) {
            float p0 = 0.0f, p1 = 0.0f;
            #pragma unroll
            for (int j = 0; j < 4; j++) {
                p0 += fmaxf(dacc[t][j][0] + bb[j][0], 0.0f) * ww[j][0];
                p0 += fmaxf(dacc[t][j][1] + bb[j][1], 0.0f) * ww[j][1];
                p1 += fmaxf(dacc[t][j][2] + bb[j][0], 0.0f) * ww[j][0];
                p1 += fmaxf(dacc[t][j][3] + bb[j][1], 0.0f) * ww[j][1];
            }
            p0 += __shfl_xor_sync(0xffffffffu, p0, 1);
            p0 += __shfl_xor_sync(0xffffffffu, p0, 2);
            p1 += __shfl_xor_sync(0xffffffffu, p1, 1);
            p1 += __shfl_xor_sync(0xffffffffu, p1, 2);
            if ((lane & 3) == 0) {
                int r = mw * 32 + 16 * t + (lane >> 2);
                sred[r + 128 * nw]     = p0;
                sred[r + 8 + 128 * nw] = p1;
            }
        }
        __syncthreads();
        if (tid < 128) {
            float l = sred[tid] + sred[tid + 128] + be2v;
            logits[e0 + tid] = l;
            probs[e0 + tid]  = 1.0f / (1.0f + expf(-l));
        }
        // next tile's post-wait sync orders sred reuse
    }
}

// ======================= launcher =======================
extern "C" void kernel_launch(void* const* d_in, const int* in_sizes, int n_in,
                              void* d_out, int out_size) {
    const float* x   = (const float*)d_in[0];
    const float* W1  = (const float*)d_in[1];
    const float* b1  = (const float*)d_in[2];
    const float* W2  = (const float*)d_in[3];
    const float* b2  = (const float*)d_in[4];
    const float* We1 = (const float*)d_in[5];
    const float* be1 = (const float*)d_in[6];
    const float* We2 = (const float*)d_in[7];
    const float* be2 = (const float*)d_in[8];
    const int*   ei  = (const int*)d_in[9];
    const int* src = ei;
    const int* dst = ei + NE;

    float* out    = (float*)d_out;
    float* H      = out;                 // [NN, 64]
    float* logits = out + NN * HID;      // [NE]
    float* probs  = logits + NE;         // [NE]

    void *yp, *h1p, *y2p, *zp, *rsp;
    cudaGetSymbolAddress(&yp, g_y);
    cudaGetSymbolAddress(&h1p, g_h1);
    cudaGetSymbolAddress(&y2p, g_y2);
    cudaGetSymbolAddress(&zp, g_zeros);
    cudaGetSymbolAddress(&rsp, g_RS);

    // CSR build (deg zeroed by previous call's k_scan23 / static init)
    k_count<<<(NE + 255) / 256, 256>>>(dst);
    k_scan1<<<NSCH, 1024>>>();
    k_scan23<<<NSCH, 1024>>>();
    k_bucket<<<(NE + 255) / 256, 256>>>(src, dst);

    int sm128 = (64 * (INDIM + 4) + 20 * (2 * INDIM + 8)) * (int)sizeof(float);
    int sm64  = (64 * (HID + 4)   + 20 * (2 * HID + 8))   * (int)sizeof(float);
    cudaFuncSetAttribute(k_gemm<INDIM>,
                         cudaFuncAttributeMaxDynamicSharedMemorySize, sm128);
    cudaFuncSetAttribute(k_gemm<HID>,
                         cudaFuncAttributeMaxDynamicSharedMemorySize, sm64);

    // encoder layer 1 (GEMM first, then 64-dim aggregation; linearity commute)
    k_gemm<INDIM><<<NN / GRT, GNT, sm128>>>(x, W1, (const float*)zp, (float*)yp);
    k_aggr<<<NN / 16, 256>>>((const float*)yp, b1, (float*)h1p);
    // encoder layer 2 -> H into d_out
    k_gemm<HID><<<NN / GRT, GNT, sm64>>>((const float*)h1p, W2, (const float*)zp,
                                         (float*)y2p);
    k_aggr<<<NN / 16, 256>>>((const float*)y2p, b2, H);

    // per-node linear halves R|S (fp16)
    k_rs<<<NN / 40, 512>>>(H, We1, (__half*)rsp);

    // fused edge MLP (K=128, cp.async pipelined mma.sync)
    cudaFuncSetAttribute(k_edge, cudaFuncAttributeMaxDynamicSharedMemorySize,
                         SMEM_EDGE);
    k_edge<<<148, 256, SMEM_EDGE>>>(H, (const __half*)rsp, src, dst,
                                    We1, be1, We2, be2, logits, probs);
}

// round 11
// speedup vs baseline: 1.1890x; 1.1890x over previous
#include <cuda_runtime.h>
#include <cuda_fp16.h>
#include <cstdint>
#include <math.h>

#define NN 50000
#define NE 800000
#define INDIM 128
#define HID 64
#define NSCH 49   // ceil(NN/1024)

// ======================= device scratch =======================
__device__ int   g_deg[NN];           // static-zeroed; re-zeroed by k_scan23
__device__ int   g_row_start[NN + 1];
__device__ int   g_cursor[NN];
__device__ int   g_csr[NE];
__device__ float g_invdeg[NN];
__device__ int   g_psum[64];
__device__ float g_y[NN * HID];
__device__ float g_h1[NN * HID];
__device__ float g_y2[NN * HID];
__device__ float g_zeros[128];

// ======================= CSR build =======================
__global__ void k_count(const int* __restrict__ dst) {
    int e = blockIdx.x * blockDim.x + threadIdx.x;
    if (e < NE) atomicAdd(&g_deg[dst[e]], 1);
}

__global__ void __launch_bounds__(1024) k_scan1() {
    __shared__ int wsum[32];
    int tid = threadIdx.x;
    int i = blockIdx.x * 1024 + tid;
    int v = (i < NN) ? g_deg[i] : 0;
    int xv = v;
    #pragma unroll
    for (int o = 1; o < 32; o <<= 1) {
        int y = __shfl_up_sync(0xffffffffu, xv, o);
        if ((tid & 31) >= o) xv += y;
    }
    if ((tid & 31) == 31) wsum[tid >> 5] = xv;
    __syncthreads();
    if (tid < 32) {
        int s = wsum[tid];
        #pragma unroll
        for (int o = 1; o < 32; o <<= 1) {
            int y = __shfl_up_sync(0xffffffffu, s, o);
            if (tid >= o) s += y;
        }
        wsum[tid] = s;
    }
    __syncthreads();
    int add = (tid >= 32) ? wsum[(tid >> 5) - 1] : 0;
    if (i < NN) g_row_start[i] = xv + add - v;
    if (tid == 0) g_psum[blockIdx.x] = wsum[31];
}

// Fused: scan the 49 chunk sums (redundantly per block) + apply + init + deg reset.
__global__ void __launch_bounds__(1024) k_scan23() {
    __shared__ int sexc[64];
    __shared__ int wtot;
    int tid = threadIdx.x;
    int v = 0, x = 0;
    if (tid < 64) {
        v = (tid < NSCH) ? g_psum[tid] : 0;
        x = v;
        #pragma unroll
        for (int o = 1; o < 32; o <<= 1) {
            int y = __shfl_up_sync(0xffffffffu, x, o);
            if ((tid & 31) >= o) x += y;
        }
        if (tid == 31) wtot = x;
    }
    __syncthreads();
    if (tid < 64) {
        int incl = x + ((tid >= 32) ? wtot : 0);
        sexc[tid] = incl - v;
        if (tid == NSCH - 1) g_row_start[NN] = incl;
    }
    __syncthreads();
    int off = sexc[blockIdx.x];
    int i = blockIdx.x * 1024 + tid;
    if (i < NN) {
        int rs = g_row_start[i] + off;
        g_row_start[i] = rs;
        g_cursor[i]    = rs;
        g_invdeg[i]    = 1.0f / fmaxf((float)g_deg[i], 1.0f);
        g_deg[i]       = 0;   // reset for next launch (deterministic)
    }
}

__global__ void k_bucket(const int* __restrict__ src, const int* __restrict__ dst) {
    int e = blockIdx.x * blockDim.x + threadIdx.x;
    if (e < NE) {
        int d = dst[e];
        int p = atomicAdd(&g_cursor[d], 1);
        g_csr[p] = src[e];
    }
}

// ======= mean aggregation (fused bias + relu): out = relu(y + agg(y)/deg + b)
__global__ void __launch_bounds__(256) k_aggr(const float* __restrict__ y,
                                              const float* __restrict__ bias,
                                              float* __restrict__ out) {
    int node = blockIdx.x * 16 + (threadIdx.x >> 4);
    int c4 = (threadIdx.x & 15) * 4;
    int beg = g_row_start[node], end = g_row_start[node + 1];
    float4 acc = make_float4(0.f, 0.f, 0.f, 0.f);
    int e = beg;
    for (; e + 7 < end; e += 8) {
        int sI[8];
        #pragma unroll
        for (int u = 0; u < 8; u++) sI[u] = __ldg(&g_csr[e + u]);
        float4 v[8];
        #pragma unroll
        for (int u = 0; u < 8; u++)
            v[u] = *reinterpret_cast<const float4*>(y + (size_t)sI[u] * 64 + c4);
        #pragma unroll
        for (int u = 0; u < 8; u++) {
            acc.x += v[u].x; acc.y += v[u].y;
            acc.z += v[u].z; acc.w += v[u].w;
        }
    }
    for (; e < end; e++) {
        int s = __ldg(&g_csr[e]);
        float4 v = *reinterpret_cast<const float4*>(y + (size_t)s * 64 + c4);
        acc.x += v.x; acc.y += v.y; acc.z += v.z; acc.w += v.w;
    }
    float inv = g_invdeg[node];
    float4 self = *reinterpret_cast<const float4*>(y + (size_t)node * 64 + c4);
    float4 b = *reinterpret_cast<const float4*>(bias + c4);
    float4 r;
    r.x = fmaxf(self.x + acc.x * inv + b.x, 0.0f);
    r.y = fmaxf(self.y + acc.y * inv + b.y, 0.0f);
    r.z = fmaxf(self.z + acc.z * inv + b.z, 0.0f);
    r.w = fmaxf(self.w + acc.w * inv + b.w, 0.0f);
    *reinterpret_cast<float4*>(out + (size_t)node * 64 + c4) = r;
}

// ============ dense GEMM with packed f32x2: out = Z @ W + bias ============
#define FMA2(c, a, b) asm("fma.rn.f32x2 %0, %1, %2, %3;" \
                          : "=l"(c) : "l"(a), "l"(b), "l"(c))
__device__ __forceinline__ unsigned long long pk(float lo, float hi) {
    unsigned long long r = (unsigned long long)__float_as_uint(lo);
    return r | ((unsigned long long)__float_as_uint(hi) << 32);
}

#define GRT 40
#define GNT 320
template <int K>
__global__ void __launch_bounds__(GNT) k_gemm(const float* __restrict__ Z,
                                              const float* __restrict__ W,
                                              const float* __restrict__ bias,
                                              float* __restrict__ out) {
    constexpr int KP = K + 4;
    constexpr int PSTR = 2 * K + 8;
    extern __shared__ float smg[];
    float* Ws  = smg;
    float* Zs2 = smg + 64 * KP;
    int tid = threadIdx.x;
    int j = tid % 64, rg = tid / 64;
    for (int idx = tid; idx < K * 64; idx += GNT) {
        int k = idx >> 6, c = idx & 63;
        Ws[c * KP + k] = W[idx];
    }
    int row0 = blockIdx.x * GRT;
    for (int idx = tid; idx < GRT * (K / 4); idx += GNT) {
        int r = idx / (K / 4), kq = idx % (K / 4);
        float4 v = reinterpret_cast<const float4*>(Z + (size_t)(row0 + r) * K)[kq];
        float* zb = Zs2 + (r >> 1) * PSTR + (r & 1) + 8 * kq;
        zb[0] = v.x; zb[2] = v.y; zb[4] = v.z; zb[6] = v.w;
    }
    __syncthreads();
    float bj = bias[j];
    unsigned long long acc2[4];
    #pragma unroll
    for (int rp = 0; rp < 4; rp++) acc2[rp] = pk(bj, bj);
    const float4* w4 = reinterpret_cast<const float4*>(&Ws[j * KP]);
    #pragma unroll 8
    for (int k4 = 0; k4 < K / 4; k4++) {
        float4 w = w4[k4];
        unsigned long long w0 = pk(w.x, w.x), w1 = pk(w.y, w.y);
        unsigned long long w2 = pk(w.z, w.z), w3 = pk(w.w, w.w);
        #pragma unroll
        for (int rp = 0; rp < 4; rp++) {
            const ulonglong2* zp = reinterpret_cast<const ulonglong2*>(
                &Zs2[(rg * 4 + rp) * PSTR + 8 * k4]);
            ulonglong2 A = zp[0], B = zp[1];
            FMA2(acc2[rp], A.x, w0);
            FMA2(acc2[rp], A.y, w1);
            FMA2(acc2[rp], B.x, w2);
            FMA2(acc2[rp], B.y, w3);
        }
    }
    #pragma unroll
    for (int rp = 0; rp < 4; rp++) {
        float lo = __uint_as_float((unsigned)acc2[rp]);
        float hi = __uint_as_float((unsigned)(acc2[rp] >> 32));
        out[(size_t)(row0 + rg * 8 + 2 * rp) * 64 + j]     = lo;
        out[(size_t)(row0 + rg * 8 + 2 * rp + 1) * 64 + j] = hi;
    }
}

// ======================= fused edge MLP: cp.async pipelined mma.sync =======================
// (R9 design: K=256 single fp16 pass; gather is H rows only — adding per-edge
// gather traffic to cut MMA was measured net-negative in R10.)
#define ET 128
#define ETILES (NE / ET)         // 6250
#define ROWB 528                 // A row: 264 halfs (8-half pad)
#define RAWB 544                 // raw: hs 256B @0, hd 256B @272 (pad for banks)
#define OFF_AH 1024
#define OFF_RAW (OFF_AH + 128 * ROWB)        // 68608
#define SMEM_EDGE (OFF_RAW + 128 * RAWB)     // 138240

__device__ __forceinline__ uint32_t smem_u32(const void* p) {
    uint32_t a;
    asm("{ .reg .u64 t; cvta.to.shared.u64 t, %1; cvt.u32.u64 %0, t; }"
        : "=r"(a) : "l"(p));
    return a;
}

#define CP16(d, s) asm volatile("cp.async.cg.shared.global [%0], [%1], 16;" \
                                :: "r"(d), "l"(s))
#define CP_COMMIT() asm volatile("cp.async.commit_group;" ::: "memory")
#define CP_WAIT0()  asm volatile("cp.async.wait_group 0;" ::: "memory")

#define LDSM4(r, addr)                                                         \
    asm volatile("ldmatrix.sync.aligned.m8n8.x4.shared.b16 {%0,%1,%2,%3}, [%4];" \
                 : "=r"((r)[0]), "=r"((r)[1]), "=r"((r)[2]), "=r"((r)[3])      \
                 : "r"(addr))

#define MMA16816(d, a, b)                                                      \
    asm volatile("mma.sync.aligned.m16n8k16.row.col.f32.f16.f16.f32 "          \
                 "{%0,%1,%2,%3},{%4,%5,%6,%7},{%8,%9},{%0,%1,%2,%3};"          \
                 : "+f"((d)[0]), "+f"((d)[1]), "+f"((d)[2]), "+f"((d)[3])      \
                 : "r"((a)[0]), "r"((a)[1]), "r"((a)[2]), "r"((a)[3]),         \
                   "r"((b)[0]), "r"((b)[1]))

__device__ __forceinline__ void write8h(char* ah, int koff2, const float* v) {
    uint32_t hi[4];
    #pragma unroll
    for (int i = 0; i < 4; i++) {
        __half2 h = __floats2half2_rn(v[2 * i], v[2 * i + 1]);
        hi[i] = *reinterpret_cast<uint32_t*>(&h);
    }
    *reinterpret_cast<uint4*>(ah + koff2) = make_uint4(hi[0], hi[1], hi[2], hi[3]);
}

__global__ void __launch_bounds__(256, 1) k_edge(
    const float* __restrict__ H, const int* __restrict__ src,
    const int* __restrict__ dst, const float* __restrict__ We1,
    const float* __restrict__ be1, const float* __restrict__ We2,
    const float* __restrict__ be2,
    float* __restrict__ logits, float* __restrict__ probs) {
    extern __shared__ char sm[];
    float* sred = reinterpret_cast<float*>(sm);
    char* AhB  = sm + OFF_AH;
    char* rawB = sm + OFF_RAW;

    int tid = threadIdx.x, lane = tid & 31, wid = tid >> 5;
    int mw = wid & 3, nw = wid >> 2;

    // ---- load B fragments into registers (once per block) ----
    uint32_t bF[16][4][2];
    #pragma unroll
    for (int s = 0; s < 16; s++)
        #pragma unroll
        for (int j = 0; j < 4; j++)
            #pragma unroll
            for (int r = 0; r < 2; r++) {
                int k = s * 16 + 2 * (lane & 3) + r * 8;
                int n = nw * 32 + j * 8 + (lane >> 2);
                __half2 h = __floats2half2_rn(__ldg(&We1[k * 64 + n]),
                                              __ldg(&We1[(k + 1) * 64 + n]));
                bF[s][j][r] = *reinterpret_cast<uint32_t*>(&h);
            }
    float bb[4][2], ww[4][2];
    #pragma unroll
    for (int j = 0; j < 4; j++)
        #pragma unroll
        for (int c = 0; c < 2; c++) {
            int nc = nw * 32 + j * 8 + 2 * (lane & 3) + c;
            bb[j][c] = __ldg(&be1[nc]);
            ww[j][c] = __ldg(&We2[nc]);
        }
    float be2v = be2[0];

    int el = tid >> 1, q = tid & 1;    // this thread owns edge el, half q
    const int* idxp = q ? dst : src;   // q=0 copies hs row, q=1 copies hd row
    uint32_t rawDst = smem_u32(rawB + el * RAWB + q * 272);
    uint32_t AhAddr = smem_u32(AhB);
    uint32_t mrow = (uint32_t)(mw * 32 + (lane & 15)) * ROWB + (lane >> 4) * 16;
    int G = gridDim.x;

    // ---- prologue: prefetch raw rows for first tile; preload next indices ----
    int tile0 = blockIdx.x;
    {
        int n0 = __ldg(&idxp[tile0 * ET + el]);
        const char* s0 = (const char*)(H + (size_t)n0 * 64);
        #pragma unroll
        for (int k = 0; k < 16; k++) CP16(rawDst + k * 16, s0 + k * 16);
        CP_COMMIT();
    }
    int tnext = tile0 + G;
    int nnext = (tnext < ETILES) ? __ldg(&idxp[tnext * ET + el]) : 0;

    for (int tile = tile0; tile < ETILES; tile += G) {
        int e0 = tile * ET;
        CP_WAIT0();
        __syncthreads();   // raw[tile] visible to all threads

        // ---- convert: raw fp32 (smem) -> fp16 A' [hs|hd|p|q] ----
        {
            const float4* rhs = reinterpret_cast<const float4*>(
                rawB + el * RAWB + q * 128);
            const float4* rhd = reinterpret_cast<const float4*>(
                rawB + el * RAWB + 272 + q * 128);
            char* rAh = AhB + el * ROWB;
            #pragma unroll
            for (int c = 0; c < 4; c++) {
                float4 a0 = rhs[2 * c], a1 = rhs[2 * c + 1];
                float4 b0 = rhd[2 * c], b1 = rhd[2 * c + 1];
                float hs8[8] = {a0.x, a0.y, a0.z, a0.w, a1.x, a1.y, a1.z, a1.w};
                float hd8[8] = {b0.x, b0.y, b0.z, b0.w, b1.x, b1.y, b1.z, b1.w};
                float p8[8], q8[8];
                #pragma unroll
                for (int i = 0; i < 8; i++) {
                    p8[i] = hs8[i] * hd8[i];
                    q8[i] = fabsf(hs8[i] - hd8[i]);
                }
                int kb = (32 * q + 8 * c) * 2;
                write8h(rAh, kb, hs8);
                write8h(rAh, kb + 128, hd8);
                write8h(rAh, kb + 256, p8);
                write8h(rAh, kb + 384, q8);
            }
        }
        __syncthreads();   // A ready; raw consumed

        // ---- prefetch raw for next tile (overlaps MMA + epilogue) ----
        int tn = tile + G;
        if (tn < ETILES) {
            const char* sN = (const char*)(H + (size_t)nnext * 64);
            #pragma unroll
            for (int k = 0; k < 16; k++) CP16(rawDst + k * 16, sN + k * 16);
            CP_COMMIT();
            int tnn = tn + G;
            if (tnn < ETILES) nnext = __ldg(&idxp[tnn * ET + el]);
        }

        // ---- MMA: K=256, single fp16 pass ----
        float dacc[2][4][4];
        #pragma unroll
        for (int t = 0; t < 2; t++)
            #pragma unroll
            for (int j = 0; j < 4; j++)
                #pragma unroll
                for (int r = 0; r < 4; r++) dacc[t][j][r] = 0.0f;

        uint32_t base = AhAddr + mrow;
        #pragma unroll
        for (int s = 0; s < 16; s++) {
            uint32_t a0[4], a1[4];
            LDSM4(a0, base + s * 32);
            LDSM4(a1, base + 16 * ROWB + s * 32);
            #pragma unroll
            for (int j = 0; j < 4; j++) {
                MMA16816(dacc[0][j], a0, bF[s][j]);
                MMA16816(dacc[1][j], a1, bF[s][j]);
            }
        }

        // ---- epilogue: relu(D+be1).We2, quad reduce, smem combine ----
        #pragma unroll
        for (int t = 0; t < 2; t++) {
            float p0 = 0.0f, p1 = 0.0f;
            #pragma unroll
            for (int j = 0; j < 4; j++) {
                p0 += fmaxf(dacc[t][j][0] + bb[j][0], 0.0f) * ww[j][0];
                p0 += fmaxf(dacc[t][j][1] + bb[j][1], 0.0f) * ww[j][1];
                p1 += fmaxf(dacc[t][j][2] + bb[j][0], 0.0f) * ww[j][0];
                p1 += fmaxf(dacc[t][j][3] + bb[j][1], 0.0f) * ww[j][1];
            }
            p0 += __shfl_xor_sync(0xffffffffu, p0, 1);
            p0 += __shfl_xor_sync(0xffffffffu, p0, 2);
            p1 += __shfl_xor_sync(0xffffffffu, p1, 1);
            p1 += __shfl_xor_sync(0xffffffffu, p1, 2);
            if ((lane & 3) == 0) {
                int r = mw * 32 + 16 * t + (lane >> 2);
                sred[r + 128 * nw]     = p0;
                sred[r + 8 + 128 * nw] = p1;
            }
        }
        __syncthreads();
        if (tid < 128) {
            float l = sred[tid] + sred[tid + 128] + be2v;
            logits[e0 + tid] = l;
            probs[e0 + tid]  = 1.0f / (1.0f + expf(-l));
        }
        // next tile's convert-phase syncs order sred reuse
    }
}

// ======================= launcher =======================
extern "C" void kernel_launch(void* const* d_in, const int* in_sizes, int n_in,
                              void* d_out, int out_size) {
    const float* x   = (const float*)d_in[0];
    const float* W1  = (const float*)d_in[1];
    const float* b1  = (const float*)d_in[2];
    const float* W2  = (const float*)d_in[3];
    const float* b2  = (const float*)d_in[4];
    const float* We1 = (const float*)d_in[5];
    const float* be1 = (const float*)d_in[6];
    const float* We2 = (const float*)d_in[7];
    const float* be2 = (const float*)d_in[8];
    const int*   ei  = (const int*)d_in[9];
    const int* src = ei;
    const int* dst = ei + NE;

    float* out    = (float*)d_out;
    float* H      = out;                 // [NN, 64]
    float* logits = out + NN * HID;      // [NE]
    float* probs  = logits + NE;         // [NE]

    void *yp, *h1p, *y2p, *zp;
    cudaGetSymbolAddress(&yp, g_y);
    cudaGetSymbolAddress(&h1p, g_h1);
    cudaGetSymbolAddress(&y2p, g_y2);
    cudaGetSymbolAddress(&zp, g_zeros);

    // CSR build (deg zeroed by previous call's k_scan23 / static init)
    k_count<<<(NE + 255) / 256, 256>>>(dst);
    k_scan1<<<NSCH, 1024>>>();
    k_scan23<<<NSCH, 1024>>>();
    k_bucket<<<(NE + 255) / 256, 256>>>(src, dst);

    int sm128 = (64 * (INDIM + 4) + 20 * (2 * INDIM + 8)) * (int)sizeof(float);
    int sm64  = (64 * (HID + 4)   + 20 * (2 * HID + 8))   * (int)sizeof(float);
    cudaFuncSetAttribute(k_gemm<INDIM>,
                         cudaFuncAttributeMaxDynamicSharedMemorySize, sm128);
    cudaFuncSetAttribute(k_gemm<HID>,
                         cudaFuncAttributeMaxDynamicSharedMemorySize, sm64);

    // encoder layer 1 (GEMM first, then 64-dim aggregation; linearity commute)
    k_gemm<INDIM><<<NN / GRT, GNT, sm128>>>(x, W1, (const float*)zp, (float*)yp);
    k_aggr<<<NN / 16, 256>>>((const float*)yp, b1, (float*)h1p);
    // encoder layer 2 -> H into d_out
    k_gemm<HID><<<NN / GRT, GNT, sm64>>>((const float*)h1p, W2, (const float*)zp,
                                         (float*)y2p);
    k_aggr<<<NN / 16, 256>>>((const float*)y2p, b2, H);

    // fused edge MLP (cp.async pipelined mma.sync, K=256)
    cudaFuncSetAttribute(k_edge, cudaFuncAttributeMaxDynamicSharedMemorySize,
                         SMEM_EDGE);
    k_edge<<<148, 256, SMEM_EDGE>>>(H, src, dst, We1, be1, We2, be2,
                                    logits, probs);
}

// round 12
// speedup vs baseline: 1.2342x; 1.0380x over previous
#include <cuda_runtime.h>
#include <cuda_fp16.h>
#include <cstdint>
#include <math.h>

#define NN 50000
#define NE 800000
#define INDIM 128
#define HID 64
#define NSCH 49   // ceil(NN/1024)

// ======================= device scratch =======================
__device__ int   g_deg[NN];           // static-zeroed; re-zeroed by k_scan23
__device__ int   g_row_start[NN + 1];
__device__ int   g_cursor[NN];
__device__ int   g_csr[NE];
__device__ float g_invdeg[NN];
__device__ int   g_psum[64];
__device__ float g_y[NN * HID];
__device__ float g_h1[NN * HID];
__device__ float g_y2[NN * HID];
__device__ float g_zeros[128];

// ======================= packed f32x2 helpers =======================
#define FMA2(c, a, b) asm("fma.rn.f32x2 %0, %1, %2, %3;" \
                          : "=l"(c) : "l"(a), "l"(b), "l"(c))
__device__ __forceinline__ unsigned long long pk(float lo, float hi) {
    unsigned long long r = (unsigned long long)__float_as_uint(lo);
    return r | ((unsigned long long)__float_as_uint(hi) << 32);
}

#define GRT 40
#define GNT 320
#define G1BLK (NN / GRT)      // 1250 gemm blocks in FK1
#define CNTBLK (NE / GNT)     // 2500 count blocks in FK1

// ============ FK1: fused [gemm layer1 (y = x@W1)] + [edge-count histogram] ============
__global__ void __launch_bounds__(GNT) k_fk1(const float* __restrict__ Z,
                                             const float* __restrict__ W,
                                             const int* __restrict__ dstE,
                                             float* __restrict__ out) {
    if (blockIdx.x >= G1BLK) {
        int e = (blockIdx.x - G1BLK) * GNT + threadIdx.x;
        if (e < NE) atomicAdd(&g_deg[dstE[e]], 1);
        return;
    }
    constexpr int K = INDIM;
    constexpr int KP = K + 4;
    constexpr int PSTR = 2 * K + 8;
    extern __shared__ float smg[];
    float* Ws  = smg;
    float* Zs2 = smg + 64 * KP;
    int tid = threadIdx.x;
    int j = tid % 64, rg = tid / 64;
    for (int idx = tid; idx < K * 64; idx += GNT) {
        int k = idx >> 6, c = idx & 63;
        Ws[c * KP + k] = W[idx];
    }
    int row0 = blockIdx.x * GRT;
    for (int idx = tid; idx < GRT * (K / 4); idx += GNT) {
        int r = idx / (K / 4), kq = idx % (K / 4);
        float4 v = reinterpret_cast<const float4*>(Z + (size_t)(row0 + r) * K)[kq];
        float* zb = Zs2 + (r >> 1) * PSTR + (r & 1) + 8 * kq;
        zb[0] = v.x; zb[2] = v.y; zb[4] = v.z; zb[6] = v.w;
    }
    __syncthreads();
    unsigned long long acc2[4];
    #pragma unroll
    for (int rp = 0; rp < 4; rp++) acc2[rp] = 0ull;
    const float4* w4 = reinterpret_cast<const float4*>(&Ws[j * KP]);
    #pragma unroll 8
    for (int k4 = 0; k4 < K / 4; k4++) {
        float4 w = w4[k4];
        unsigned long long w0 = pk(w.x, w.x), w1 = pk(w.y, w.y);
        unsigned long long w2 = pk(w.z, w.z), w3 = pk(w.w, w.w);
        #pragma unroll
        for (int rp = 0; rp < 4; rp++) {
            const ulonglong2* zp = reinterpret_cast<const ulonglong2*>(
                &Zs2[(rg * 4 + rp) * PSTR + 8 * k4]);
            ulonglong2 A = zp[0], B = zp[1];
            FMA2(acc2[rp], A.x, w0);
            FMA2(acc2[rp], A.y, w1);
            FMA2(acc2[rp], B.x, w2);
            FMA2(acc2[rp], B.y, w3);
        }
    }
    #pragma unroll
    for (int rp = 0; rp < 4; rp++) {
        float lo = __uint_as_float((unsigned)acc2[rp]);
        float hi = __uint_as_float((unsigned)(acc2[rp] >> 32));
        out[(size_t)(row0 + rg * 8 + 2 * rp) * 64 + j]     = lo;
        out[(size_t)(row0 + rg * 8 + 2 * rp + 1) * 64 + j] = hi;
    }
}

// ======================= CSR scan =======================
__global__ void __launch_bounds__(1024) k_scan1() {
    __shared__ int wsum[32];
    int tid = threadIdx.x;
    int i = blockIdx.x * 1024 + tid;
    int v = (i < NN) ? g_deg[i] : 0;
    int xv = v;
    #pragma unroll
    for (int o = 1; o < 32; o <<= 1) {
        int y = __shfl_up_sync(0xffffffffu, xv, o);
        if ((tid & 31) >= o) xv += y;
    }
    if ((tid & 31) == 31) wsum[tid >> 5] = xv;
    __syncthreads();
    if (tid < 32) {
        int s = wsum[tid];
        #pragma unroll
        for (int o = 1; o < 32; o <<= 1) {
            int y = __shfl_up_sync(0xffffffffu, s, o);
            if (tid >= o) s += y;
        }
        wsum[tid] = s;
    }
    __syncthreads();
    int add = (tid >= 32) ? wsum[(tid >> 5) - 1] : 0;
    if (i < NN) g_row_start[i] = xv + add - v;
    if (tid == 0) g_psum[blockIdx.x] = wsum[31];
}

__global__ void __launch_bounds__(1024) k_scan23() {
    __shared__ int sexc[64];
    __shared__ int wtot;
    int tid = threadIdx.x;
    int v = 0, x = 0;
    if (tid < 64) {
        v = (tid < NSCH) ? g_psum[tid] : 0;
        x = v;
        #pragma unroll
        for (int o = 1; o < 32; o <<= 1) {
            int y = __shfl_up_sync(0xffffffffu, x, o);
            if ((tid & 31) >= o) x += y;
        }
        if (tid == 31) wtot = x;
    }
    __syncthreads();
    if (tid < 64) {
        int incl = x + ((tid >= 32) ? wtot : 0);
        sexc[tid] = incl - v;
        if (tid == NSCH - 1) g_row_start[NN] = incl;
    }
    __syncthreads();
    int off = sexc[blockIdx.x];
    int i = blockIdx.x * 1024 + tid;
    if (i < NN) {
        int rs = g_row_start[i] + off;
        g_row_start[i] = rs;
        g_cursor[i]    = rs;
        g_invdeg[i]    = 1.0f / fmaxf((float)g_deg[i], 1.0f);
        g_deg[i]       = 0;   // reset for next launch (deterministic)
    }
}

__global__ void k_bucket(const int* __restrict__ src, const int* __restrict__ dst) {
    int e = blockIdx.x * blockDim.x + threadIdx.x;
    if (e < NE) {
        int d = dst[e];
        int p = atomicAdd(&g_cursor[d], 1);
        g_csr[p] = src[e];
    }
}

// ======= mean aggregation (fused bias + relu): out = relu(y + agg(y)/deg + b)
__global__ void __launch_bounds__(256) k_aggr(const float* __restrict__ y,
                                              const float* __restrict__ bias,
                                              float* __restrict__ out) {
    int node = blockIdx.x * 16 + (threadIdx.x >> 4);
    int c4 = (threadIdx.x & 15) * 4;
    int beg = g_row_start[node], end = g_row_start[node + 1];
    float4 acc = make_float4(0.f, 0.f, 0.f, 0.f);
    int e = beg;
    for (; e + 7 < end; e += 8) {
        int sI[8];
        #pragma unroll
        for (int u = 0; u < 8; u++) sI[u] = __ldg(&g_csr[e + u]);
        float4 v[8];
        #pragma unroll
        for (int u = 0; u < 8; u++)
            v[u] = *reinterpret_cast<const float4*>(y + (size_t)sI[u] * 64 + c4);
        #pragma unroll
        for (int u = 0; u < 8; u++) {
            acc.x += v[u].x; acc.y += v[u].y;
            acc.z += v[u].z; acc.w += v[u].w;
        }
    }
    for (; e < end; e++) {
        int s = __ldg(&g_csr[e]);
        float4 v = *reinterpret_cast<const float4*>(y + (size_t)s * 64 + c4);
        acc.x += v.x; acc.y += v.y; acc.z += v.z; acc.w += v.w;
    }
    float inv = g_invdeg[node];
    float4 self = *reinterpret_cast<const float4*>(y + (size_t)node * 64 + c4);
    float4 b = *reinterpret_cast<const float4*>(bias + c4);
    float4 r;
    r.x = fmaxf(self.x + acc.x * inv + b.x, 0.0f);
    r.y = fmaxf(self.y + acc.y * inv + b.y, 0.0f);
    r.z = fmaxf(self.z + acc.z * inv + b.z, 0.0f);
    r.w = fmaxf(self.w + acc.w * inv + b.w, 0.0f);
    *reinterpret_cast<float4*>(out + (size_t)node * 64 + c4) = r;
}

// ============ dense GEMM (layer 2) with packed f32x2 ============
template <int K>
__global__ void __launch_bounds__(GNT) k_gemm(const float* __restrict__ Z,
                                              const float* __restrict__ W,
                                              const float* __restrict__ bias,
                                              float* __restrict__ out) {
    constexpr int KP = K + 4;
    constexpr int PSTR = 2 * K + 8;
    extern __shared__ float smg[];
    float* Ws  = smg;
    float* Zs2 = smg + 64 * KP;
    int tid = threadIdx.x;
    int j = tid % 64, rg = tid / 64;
    for (int idx = tid; idx < K * 64; idx += GNT) {
        int k = idx >> 6, c = idx & 63;
        Ws[c * KP + k] = W[idx];
    }
    int row0 = blockIdx.x * GRT;
    for (int idx = tid; idx < GRT * (K / 4); idx += GNT) {
        int r = idx / (K / 4), kq = idx % (K / 4);
        float4 v = reinterpret_cast<const float4*>(Z + (size_t)(row0 + r) * K)[kq];
        float* zb = Zs2 + (r >> 1) * PSTR + (r & 1) + 8 * kq;
        zb[0] = v.x; zb[2] = v.y; zb[4] = v.z; zb[6] = v.w;
    }
    __syncthreads();
    float bj = bias[j];
    unsigned long long acc2[4];
    #pragma unroll
    for (int rp = 0; rp < 4; rp++) acc2[rp] = pk(bj, bj);
    const float4* w4 = reinterpret_cast<const float4*>(&Ws[j * KP]);
    #pragma unroll 8
    for (int k4 = 0; k4 < K / 4; k4++) {
        float4 w = w4[k4];
        unsigned long long w0 = pk(w.x, w.x), w1 = pk(w.y, w.y);
        unsigned long long w2 = pk(w.z, w.z), w3 = pk(w.w, w.w);
        #pragma unroll
        for (int rp = 0; rp < 4; rp++) {
            const ulonglong2* zp = reinterpret_cast<const ulonglong2*>(
                &Zs2[(rg * 4 + rp) * PSTR + 8 * k4]);
            ulonglong2 A = zp[0], B = zp[1];
            FMA2(acc2[rp], A.x, w0);
            FMA2(acc2[rp], A.y, w1);
            FMA2(acc2[rp], B.x, w2);
            FMA2(acc2[rp], B.y, w3);
        }
    }
    #pragma unroll
    for (int rp = 0; rp < 4; rp++) {
        float lo = __uint_as_float((unsigned)acc2[rp]);
        float hi = __uint_as_float((unsigned)(acc2[rp] >> 32));
        out[(size_t)(row0 + rg * 8 + 2 * rp) * 64 + j]     = lo;
        out[(size_t)(row0 + rg * 8 + 2 * rp + 1) * 64 + j] = hi;
    }
}

// ======================= fused edge MLP: interleaved-convert pipelined mma.sync ======
// Double-buffered A; convert(t+1) chunks woven INTO the MMA(t) loop so the
// FMA/LSU pipes run under the tensor phase. K=256, single fp16 pass.
#define ET 128
#define ETILES (NE / ET)         // 6250
#define ROWB 528                 // A row: 264 halfs (8-half pad)
#define RAWB 544                 // raw: hs 256B @0, hd 256B @272
#define OFF_A0 1024
#define OFF_A1 (OFF_A0 + 128 * ROWB)         // 68608
#define OFF_RAW (OFF_A1 + 128 * ROWB)        // 136192
#define SMEM_EDGE (OFF_RAW + 128 * RAWB)     // 205824

__device__ __forceinline__ uint32_t smem_u32(const void* p) {
    uint32_t a;
    asm("{ .reg .u64 t; cvta.to.shared.u64 t, %1; cvt.u32.u64 %0, t; }"
        : "=r"(a) : "l"(p));
    return a;
}

#define CP16(d, s) asm volatile("cp.async.cg.shared.global [%0], [%1], 16;" \
                                :: "r"(d), "l"(s))
#define CP_COMMIT() asm volatile("cp.async.commit_group;" ::: "memory")
#define CP_WAIT0()  asm volatile("cp.async.wait_group 0;" ::: "memory")

#define LDSM4(r, addr)                                                         \
    asm volatile("ldmatrix.sync.aligned.m8n8.x4.shared.b16 {%0,%1,%2,%3}, [%4];" \
                 : "=r"((r)[0]), "=r"((r)[1]), "=r"((r)[2]), "=r"((r)[3])      \
                 : "r"(addr))

#define MMA16816(d, a, b)                                                      \
    asm volatile("mma.sync.aligned.m16n8k16.row.col.f32.f16.f16.f32 "          \
                 "{%0,%1,%2,%3},{%4,%5,%6,%7},{%8,%9},{%0,%1,%2,%3};"          \
                 : "+f"((d)[0]), "+f"((d)[1]), "+f"((d)[2]), "+f"((d)[3])      \
                 : "r"((a)[0]), "r"((a)[1]), "r"((a)[2]), "r"((a)[3]),         \
                   "r"((b)[0]), "r"((b)[1]))

__device__ __forceinline__ void write8h(char* ah, int koff2, const float* v) {
    uint32_t hi[4];
    #pragma unroll
    for (int i = 0; i < 4; i++) {
        __half2 h = __floats2half2_rn(v[2 * i], v[2 * i + 1]);
        hi[i] = *reinterpret_cast<uint32_t*>(&h);
    }
    *reinterpret_cast<uint4*>(ah + koff2) = make_uint4(hi[0], hi[1], hi[2], hi[3]);
}

// convert chunk c for thread (el,q): raw fp32 -> fp16 [hs|hd|p|q] row of A
__device__ __forceinline__ void conv_chunk(const char* rawB, char* rA,
                                           int el, int q, int c) {
    const float4* rhs = reinterpret_cast<const float4*>(rawB + el * RAWB + q * 128);
    const float4* rhd = reinterpret_cast<const float4*>(rawB + el * RAWB + 272 + q * 128);
    float4 a0 = rhs[2 * c], a1 = rhs[2 * c + 1];
    float4 b0 = rhd[2 * c], b1 = rhd[2 * c + 1];
    float hs8[8] = {a0.x, a0.y, a0.z, a0.w, a1.x, a1.y, a1.z, a1.w};
    float hd8[8] = {b0.x, b0.y, b0.z, b0.w, b1.x, b1.y, b1.z, b1.w};
    float p8[8], q8[8];
    #pragma unroll
    for (int i = 0; i < 8; i++) {
        p8[i] = hs8[i] * hd8[i];
        q8[i] = fabsf(hs8[i] - hd8[i]);
    }
    int kb = (32 * q + 8 * c) * 2;
    write8h(rA, kb, hs8);
    write8h(rA, kb + 128, hd8);
    write8h(rA, kb + 256, p8);
    write8h(rA, kb + 384, q8);
}

__global__ void __launch_bounds__(256, 1) k_edge(
    const float* __restrict__ H, const int* __restrict__ src,
    const int* __restrict__ dst, const float* __restrict__ We1,
    const float* __restrict__ be1, const float* __restrict__ We2,
    const float* __restrict__ be2,
    float* __restrict__ logits, float* __restrict__ probs) {
    extern __shared__ char sm[];
    float* sred = reinterpret_cast<float*>(sm);
    char* A0B  = sm + OFF_A0;
    char* A1B  = sm + OFF_A1;
    char* rawB = sm + OFF_RAW;

    int tid = threadIdx.x, lane = tid & 31, wid = tid >> 5;
    int mw = wid & 3, nw = wid >> 2;

    // ---- B fragments in registers (once per block) ----
    uint32_t bF[16][4][2];
    #pragma unroll
    for (int s = 0; s < 16; s++)
        #pragma unroll
        for (int j = 0; j < 4; j++)
            #pragma unroll
            for (int r = 0; r < 2; r++) {
                int k = s * 16 + 2 * (lane & 3) + r * 8;
                int n = nw * 32 + j * 8 + (lane >> 2);
                __half2 h = __floats2half2_rn(__ldg(&We1[k * 64 + n]),
                                              __ldg(&We1[(k + 1) * 64 + n]));
                bF[s][j][r] = *reinterpret_cast<uint32_t*>(&h);
            }
    float bb[4][2], ww[4][2];
    #pragma unroll
    for (int j = 0; j < 4; j++)
        #pragma unroll
        for (int c = 0; c < 2; c++) {
            int nc = nw * 32 + j * 8 + 2 * (lane & 3) + c;
            bb[j][c] = __ldg(&be1[nc]);
            ww[j][c] = __ldg(&We2[nc]);
        }
    float be2v = be2[0];

    int el = tid >> 1, q = tid & 1;
    const int* idxp = q ? dst : src;   // q=0: hs row, q=1: hd row
    uint32_t rawDst = smem_u32(rawB + el * RAWB + q * 272);
    uint32_t Aaddr[2] = {smem_u32(A0B), smem_u32(A1B)};
    char* Abuf[2] = {A0B, A1B};
    uint32_t mrow = (uint32_t)(mw * 32 + (lane & 15)) * ROWB + (lane >> 4) * 16;
    int G = gridDim.x;

    // ---- prologue: raw(t0) -> convert(t0) into A0; prefetch raw(t1) ----
    int tile0 = blockIdx.x;
    {
        int n0 = __ldg(&idxp[tile0 * ET + el]);
        const char* s0 = (const char*)(H + (size_t)n0 * 64);
        #pragma unroll
        for (int k = 0; k < 16; k++) CP16(rawDst + k * 16, s0 + k * 16);
        CP_COMMIT();
    }
    int t1 = tile0 + G;
    int n1 = (t1 < ETILES) ? __ldg(&idxp[t1 * ET + el]) : 0;
    CP_WAIT0();
    __syncthreads();
    {
        char* rA = A0B + el * ROWB;
        #pragma unroll
        for (int c = 0; c < 4; c++) conv_chunk(rawB, rA, el, q, c);
    }
    __syncthreads();   // A0 ready; raw consumable
    if (t1 < ETILES) {
        const char* sN = (const char*)(H + (size_t)n1 * 64);
        #pragma unroll
        for (int k = 0; k < 16; k++) CP16(rawDst + k * 16, sN + k * 16);
        CP_COMMIT();
    }
    int t2 = t1 + G;
    int n2 = (t2 < ETILES) ? __ldg(&idxp[t2 * ET + el]) : 0;

    int b = 0;
    for (int tile = tile0; tile < ETILES; tile += G) {
        int e0 = tile * ET;
        int hasNext = (tile + G < ETILES);
        CP_WAIT0();
        __syncthreads();   // raw(t+G) visible; prev sred reads done

        // ---- MMA(t) from A[b], interleaved convert(t+G) into A[b^1] ----
        float dacc[2][4][4];
        #pragma unroll
        for (int t = 0; t < 2; t++)
            #pragma unroll
            for (int j = 0; j < 4; j++)
                #pragma unroll
                for (int r = 0; r < 4; r++) dacc[t][j][r] = 0.0f;

        uint32_t base = Aaddr[b] + mrow;
        char* rAother = Abuf[b ^ 1] + el * ROWB;
        #pragma unroll
        for (int s = 0; s < 16; s++) {
            uint32_t a0[4], a1[4];
            LDSM4(a0, base + s * 32);
            LDSM4(a1, base + 16 * ROWB + s * 32);
            #pragma unroll
            for (int j = 0; j < 4; j++) {
                MMA16816(dacc[0][j], a0, bF[s][j]);
                MMA16816(dacc[1][j], a1, bF[s][j]);
            }
            if ((s & 3) == 0 && hasNext)
                conv_chunk(rawB, rAother, el, q, s >> 2);
        }

        // ---- epilogue: relu(D+be1).We2, quad reduce, smem combine ----
        #pragma unroll
        for (int t = 0; t < 2; t++) {
            float p0 = 0.0f, p1 = 0.0f;
            #pragma unroll
            for (int j = 0; j < 4; j++) {
                p0 += fmaxf(dacc[t][j][0] + bb[j][0], 0.0f) * ww[j][0];
                p0 += fmaxf(dacc[t][j][1] + bb[j][1], 0.0f) * ww[j][1];
                p1 += fmaxf(dacc[t][j][2] + bb[j][0], 0.0f) * ww[j][0];
                p1 += fmaxf(dacc[t][j][3] + bb[j][1], 0.0f) * ww[j][1];
            }
            p0 += __shfl_xor_sync(0xffffffffu, p0, 1);
            p0 += __shfl_xor_sync(0xffffffffu, p0, 2);
            p1 += __shfl_xor_sync(0xffffffffu, p1, 1);
            p1 += __shfl_xor_sync(0xffffffffu, p1, 2);
            if ((lane & 3) == 0) {
                int r = mw * 32 + 16 * t + (lane >> 2);
                sred[r + 128 * nw]     = p0;
                sred[r + 8 + 128 * nw] = p1;
            }
        }
        __syncthreads();   // sred ready; convert(t+G) done -> raw reusable

        // ---- prefetch raw(t+2G) (overlaps logits write + next wait) ----
        if (t2 < ETILES && tile + G < ETILES) {
            // note: t2 tracks tile+2G for the CURRENT iteration
        }
        int tnn = tile + 2 * G;
        if (tnn < ETILES) {
            const char* sN = (const char*)(H + (size_t)n2 * 64);
            #pragma unroll
            for (int k = 0; k < 16; k++) CP16(rawDst + k * 16, sN + k * 16);
            CP_COMMIT();
            int tnnn = tile + 3 * G;
            if (tnnn < ETILES) n2 = __ldg(&idxp[tnnn * ET + el]);
        }

        if (tid < 128) {
            float l = sred[tid] + sred[tid + 128] + be2v;
            logits[e0 + tid] = l;
            probs[e0 + tid]  = 1.0f / (1.0f + expf(-l));
        }
        b ^= 1;
    }
}

// ======================= launcher =======================
extern "C" void kernel_launch(void* const* d_in, const int* in_sizes, int n_in,
                              void* d_out, int out_size) {
    const float* x   = (const float*)d_in[0];
    const float* W1  = (const float*)d_in[1];
    const float* b1  = (const float*)d_in[2];
    const float* W2  = (const float*)d_in[3];
    const float* b2  = (const float*)d_in[4];
    const float* We1 = (const float*)d_in[5];
    const float* be1 = (const float*)d_in[6];
    const float* We2 = (const float*)d_in[7];
    const float* be2 = (const float*)d_in[8];
    const int*   ei  = (const int*)d_in[9];
    const int* src = ei;
    const int* dst = ei + NE;

    float* out    = (float*)d_out;
    float* H      = out;                 // [NN, 64]
    float* logits = out + NN * HID;      // [NE]
    float* probs  = logits + NE;         // [NE]

    void *yp, *h1p, *y2p, *zp;
    cudaGetSymbolAddress(&yp, g_y);
    cudaGetSymbolAddress(&h1p, g_h1);
    cudaGetSymbolAddress(&y2p, g_y2);
    cudaGetSymbolAddress(&zp, g_zeros);

    int sm128 = (64 * (INDIM + 4) + 20 * (2 * INDIM + 8)) * (int)sizeof(float);
    int sm64  = (64 * (HID + 4)   + 20 * (2 * HID + 8))   * (int)sizeof(float);
    cudaFuncSetAttribute(k_fk1,
                         cudaFuncAttributeMaxDynamicSharedMemorySize, sm128);
    cudaFuncSetAttribute(k_gemm<HID>,
                         cudaFuncAttributeMaxDynamicSharedMemorySize, sm64);

    // FK1: gemm layer1 (y = x@W1) + edge-count histogram (independent work)
    k_fk1<<<G1BLK + CNTBLK, GNT, sm128>>>(x, W1, dst, (float*)yp);
    // CSR scan + bucket
    k_scan1<<<NSCH, 1024>>>();
    k_scan23<<<NSCH, 1024>>>();
    k_bucket<<<(NE + 255) / 256, 256>>>(src, dst);
    // layer 1 aggregation, layer 2
    k_aggr<<<NN / 16, 256>>>((const float*)yp, b1, (float*)h1p);
    k_gemm<HID><<<NN / GRT, GNT, sm64>>>((const float*)h1p, W2, (const float*)zp,
                                         (float*)y2p);
    k_aggr<<<NN / 16, 256>>>((const float*)y2p, b2, H);

    // fused edge MLP (interleaved-convert pipelined mma.sync, K=256)
    cudaFuncSetAttribute(k_edge, cudaFuncAttributeMaxDynamicSharedMemorySize,
                         SMEM_EDGE);
    k_edge<<<148, 256, SMEM_EDGE>>>(H, src, dst, We1, be1, We2, be2,
                                    logits, probs);
}